// round 13
// baseline (speedup 1.0000x reference)
#include <cuda_runtime.h>
#include <cuda_bf16.h>
#include <cstdint>
#include <cstddef>

#define BB 4096
#define LL 50
#define NN 50
#define DD 128
#define PK 136                    // padded row stride (elements) -> 272B = 17*16: LDSM-aligned, conflict-free
#define TILE4 2176                // float4s per bf16 tile image (128*PK*2/16)
#define TPB 512

// ---- main-kernel smem layout (byte offsets) ----
#define WS_HI 0
#define WS_LO 34816
#define A_HI  69632
#define A_LO  104448
#define AUX   139264
#define AUX_CNT   (AUX + 0)       // int[4][64]
#define AUX_WA    (AUX + 1024)    // float[128]
#define AUX_VNP   (AUX + 1536)    // float[4][128]
#define AUX_ALPHA (AUX + 3584)    // float[4][64]
#define AUX_PART  (AUX + 4608)    // float[128][16]
#define SMEM_TOTAL (AUX + 12800)  // 152064

__device__ float g_vnp[BB * DD];
__device__ __align__(16) __nv_bfloat16 g_ws_hi[128 * PK];   // [n][k] transposed W_seq, hi
__device__ __align__(16) __nv_bfloat16 g_ws_lo[128 * PK];   // lo

__device__ __forceinline__ uint32_t smem_u32(const void* p) {
    uint32_t a;
    asm("{ .reg .u64 t; cvta.to.shared.u64 t, %1; cvt.u32.u64 %0, t; }" : "=r"(a) : "l"(p));
    return a;
}
__device__ __forceinline__ void ldsm_x4(uint32_t& r0, uint32_t& r1, uint32_t& r2, uint32_t& r3, uint32_t addr) {
    asm volatile("ldmatrix.sync.aligned.m8n8.x4.shared.b16 {%0,%1,%2,%3}, [%4];"
                 : "=r"(r0), "=r"(r1), "=r"(r2), "=r"(r3) : "r"(addr));
}
__device__ __forceinline__ void ldsm_x2(uint32_t& r0, uint32_t& r1, uint32_t addr) {
    asm volatile("ldmatrix.sync.aligned.m8n8.x2.shared.b16 {%0,%1}, [%2];"
                 : "=r"(r0), "=r"(r1) : "r"(addr));
}
__device__ __forceinline__ void mma_bf16(float* d, uint32_t a0, uint32_t a1, uint32_t a2, uint32_t a3,
                                         uint32_t b0, uint32_t b1) {
    asm volatile("mma.sync.aligned.m16n8k16.row.col.f32.bf16.bf16.f32 "
                 "{%0,%1,%2,%3}, {%4,%5,%6,%7}, {%8,%9}, {%0,%1,%2,%3};"
                 : "+f"(d[0]), "+f"(d[1]), "+f"(d[2]), "+f"(d[3])
                 : "r"(a0), "r"(a1), "r"(a2), "r"(a3), "r"(b0), "r"(b1));
}
__device__ __forceinline__ float sigf(float z) {
    return 1.0f / (1.0f + __expf(-z));
}
__device__ __forceinline__ void cp_async16(uint32_t saddr, const void* gaddr) {
    asm volatile("cp.async.cg.shared.global [%0], [%1], 16;" :: "r"(saddr), "l"(gaddr));
}

// ============================================================
// Combo kernel: blocks 0..127 -> vn (32 batches each, W_last staged);
//               blocks 128..159 -> prep W_seq split images.
// ============================================================
#define VN_SMEM ((16384 + 128 + 8 * 128) * 4)
__global__ __launch_bounds__(256)
void combo_kernel(
    const int*   __restrict__ seq,
    const int*   __restrict__ mask,
    const float* __restrict__ nodes,
    const float* __restrict__ W_last,
    const float* __restrict__ W_seq,
    const float* __restrict__ b_seq,
    float*       __restrict__ out)
{
    extern __shared__ float dsm[];
    const int tid = threadIdx.x, wid = tid >> 5, lane = tid & 31;

    if (blockIdx.x >= 128) {
        // ---- prep: bake W_seq^T split-bf16 [n][k], stride PK ----
        const int base = (blockIdx.x - 128) * 512 + tid * 2;
        #pragma unroll
        for (int j = 0; j < 2; j++) {
            const int t = base + j;          // 0..16383
            const int k = t & 127, n = t >> 7;
            const float w = W_seq[k * DD + n];
            const __nv_bfloat16 h = __float2bfloat16(w);
            g_ws_hi[n * PK + k] = h;
            g_ws_lo[n * PK + k] = __float2bfloat16(w - __bfloat162float(h));
        }
        return;
    }

    // ---- vn: 32 batches per block ----
    float* wl_s = dsm;               // 16384
    float* bs_s = dsm + 16384;       // 128
    float* vnb  = dsm + 16512;       // 8 warps * 128
    const int b0 = blockIdx.x * 32;

    #pragma unroll
    for (int i = tid; i < 4096; i += 256)
        ((float4*)wl_s)[i] = ((const float4*)W_last)[i];
    if (tid < DD) bs_s[tid] = b_seq[tid];
    __syncthreads();

    for (int r = 0; r < 4; r++) {
        const int b = b0 + wid * 4 + r;
        int cnt = ((lane      < LL) ? mask[b * LL + lane]      : 0)
                + ((lane + 32 < LL) ? mask[b * LL + lane + 32] : 0);
        #pragma unroll
        for (int off = 16; off > 0; off >>= 1)
            cnt += __shfl_xor_sync(0xffffffffu, cnt, off);
        int last = 0;
        if (lane == 0)
            last = seq[b * LL + ((cnt > 0) ? cnt - 1 : LL - 1)];
        last = __shfl_sync(0xffffffffu, last, 0);

        const float4 v = ((const float4*)(nodes + (size_t)b * NN * DD + (size_t)last * DD))[lane];
        ((float4*)(out + (size_t)b * DD))[lane] = v;       // v_n output (exact copy)
        ((float4*)(vnb + wid * 128))[lane] = v;
        __syncwarp();

        float a0 = 0.f, a1 = 0.f, a2 = 0.f, a3 = 0.f;
        const float* vr = vnb + wid * 128;
        #pragma unroll 4
        for (int k = 0; k < 128; k++) {
            const float vk = vr[k];
            const float* wr = wl_s + k * 128 + lane;
            a0 = fmaf(vk, wr[0],  a0);
            a1 = fmaf(vk, wr[32], a1);
            a2 = fmaf(vk, wr[64], a2);
            a3 = fmaf(vk, wr[96], a3);
        }
        float* gv = g_vnp + (size_t)b * DD + lane;
        gv[0]  = a0 + bs_s[lane];
        gv[32] = a1 + bs_s[lane + 32];
        gv[64] = a2 + bs_s[lane + 64];
        gv[96] = a3 + bs_s[lane + 96];
        __syncwarp();
    }
}

// ============================================================
// Main: 4 batches/CTA (two A-phases), 512 threads / 16 warps,
// each warp: 7 m-tiles x 1 n-tile (8 cols). W staged via cp.async.
// ============================================================
__global__ __launch_bounds__(TPB, 1)
void session_mma_kernel(
    const int*   __restrict__ seq,
    const int*   __restrict__ mask,
    const float* __restrict__ nodes,
    const float* __restrict__ W_alpha,
    float*       __restrict__ out)
{
    extern __shared__ char smem[];
    const uint32_t sb = smem_u32(smem);
    const int tid = threadIdx.x, wid = tid >> 5, lane = tid & 31;
    const int b0 = 4 * blockIdx.x;

    int*   cnt_s   = (int*)  (smem + AUX_CNT);
    float* wa_s    = (float*)(smem + AUX_WA);
    float* vnp_s   = (float*)(smem + AUX_VNP);
    float* alpha_s = (float*)(smem + AUX_ALPHA);
    float* part    = (float*)(smem + AUX_PART);

    // ---- kick off W image staging via cp.async (waited before phase-0 sync) ----
    {
        for (int i = tid; i < TILE4; i += TPB) {
            cp_async16(sb + WS_HI + i * 16, (const char*)g_ws_hi + i * 16);
            cp_async16(sb + WS_LO + i * 16, (const char*)g_ws_lo + i * 16);
        }
        asm volatile("cp.async.commit_group;");
    }

    if (tid < 256) cnt_s[tid] = 0;        // 4*64 ints
    if (tid < 128) wa_s[tid] = W_alpha[tid];
    // vnp for 4 batches (from combo kernel)
    vnp_s[tid] = g_vnp[(size_t)(b0 + (tid >> 7)) * DD + (tid & 127)];
    __syncthreads();

    // masked counts for 4 batches
    if (tid < 4 * LL) {
        const int bl = tid / LL, pos = tid % LL;
        const int g = (b0 + bl) * LL + pos;
        if (mask[g]) atomicAdd(&cnt_s[bl * 64 + seq[g]], 1);
    }
    // zero pad A rows 100..127 once (never overwritten by node conversion)
    for (int i = 1700 + tid; i < TILE4; i += TPB) {
        ((float4*)(smem + A_HI))[i] = make_float4(0.f, 0.f, 0.f, 0.f);
        ((float4*)(smem + A_LO))[i] = make_float4(0.f, 0.f, 0.f, 0.f);
    }

    const int lr  = lane & 7;
    const int g8  = (lane >> 3) & 1;
    const int g16 = lane >> 4;
    const int nbase = wid * 8;            // 16 warps x 8 cols = 128
    const uint32_t aRow  = (uint32_t)(8 * g8 + lr) * (PK * 2) + (uint32_t)g16 * 16;
    const uint32_t bRowB = (uint32_t)(nbase + lr) * (PK * 2) + (uint32_t)g8 * 16;  // x2: lanes 0-15

    #pragma unroll 1
    for (int ph = 0; ph < 2; ph++) {
        const int pb = b0 + 2 * ph;

        // ---- stage A: nodes (rows 0..99) -> split bf16, stride PK ----
        {
            const float4* nv = (const float4*)(nodes + (size_t)pb * NN * DD);
            #pragma unroll 2
            for (int i = tid; i < 3200; i += TPB) {
                const float4 x = nv[i];
                const int e = i * 4, row = e >> 7, k = e & 127;
                const __nv_bfloat16 h0 = __float2bfloat16(x.x);
                const __nv_bfloat16 h1 = __float2bfloat16(x.y);
                const __nv_bfloat16 h2 = __float2bfloat16(x.z);
                const __nv_bfloat16 h3 = __float2bfloat16(x.w);
                const __nv_bfloat16 l0 = __float2bfloat16(x.x - __bfloat162float(h0));
                const __nv_bfloat16 l1 = __float2bfloat16(x.y - __bfloat162float(h1));
                const __nv_bfloat16 l2 = __float2bfloat16(x.z - __bfloat162float(h2));
                const __nv_bfloat16 l3 = __float2bfloat16(x.w - __bfloat162float(h3));
                uint2 vh, vl;
                vh.x = (uint32_t)__bfloat16_as_ushort(h0) | ((uint32_t)__bfloat16_as_ushort(h1) << 16);
                vh.y = (uint32_t)__bfloat16_as_ushort(h2) | ((uint32_t)__bfloat16_as_ushort(h3) << 16);
                vl.x = (uint32_t)__bfloat16_as_ushort(l0) | ((uint32_t)__bfloat16_as_ushort(l1) << 16);
                vl.y = (uint32_t)__bfloat16_as_ushort(l2) | ((uint32_t)__bfloat16_as_ushort(l3) << 16);
                const uint32_t off = (uint32_t)row * (PK * 2) + (uint32_t)k * 2;  // 8B aligned
                *(uint2*)(smem + A_HI + off) = vh;
                *(uint2*)(smem + A_LO + off) = vl;
            }
        }
        if (ph == 0) asm volatile("cp.async.wait_group 0;" ::: "memory");
        __syncthreads();

        // ---- mma.sync mainloop: 7 m-tiles x 1 n-tile per warp, 8 k-steps, 3 passes ----
        float d[7][4];
        #pragma unroll
        for (int mt = 0; mt < 7; mt++)
            #pragma unroll
            for (int e = 0; e < 4; e++) d[mt][e] = 0.f;

        #pragma unroll
        for (int pass = 0; pass < 3; pass++) {
            const uint32_t Ab = sb + ((pass == 2) ? A_LO : A_HI);
            const uint32_t Bb = sb + ((pass == 1) ? WS_LO : WS_HI);
            #pragma unroll
            for (int ks = 0; ks < 8; ks++) {
                const uint32_t kb = (uint32_t)ks * 32;   // 16 elems * 2B
                uint32_t w0, w1;
                ldsm_x2(w0, w1, Bb + bRowB + kb);
                #pragma unroll
                for (int mt = 0; mt < 7; mt++) {
                    uint32_t a0, a1, a2, a3;
                    ldsm_x4(a0, a1, a2, a3, Ab + aRow + (uint32_t)mt * (16 * PK * 2) + kb);
                    mma_bf16(d[mt], a0, a1, a2, a3, w0, w1);
                }
            }
        }

        // ---- epilogue: sigmoid, scale by W_alpha, row-wise reduce ----
        {
            const int q = lane & 3;
            const int c = nbase + 2 * q;
            const float wa0 = wa_s[c], wa1 = wa_s[c + 1];
            #pragma unroll
            for (int mt = 0; mt < 7; mt++) {
                const int r0 = 16 * mt + (lane >> 2);
                const int r1 = r0 + 8;
                const float* vp0 = vnp_s + (2 * ph + ((r0 < 50) ? 0 : 1)) * 128;
                const float* vp1 = vnp_s + (2 * ph + ((r1 < 50) ? 0 : 1)) * 128;
                float p0 = sigf(vp0[c] + d[mt][0]) * wa0 + sigf(vp0[c + 1] + d[mt][1]) * wa1;
                float p1 = sigf(vp1[c] + d[mt][2]) * wa0 + sigf(vp1[c + 1] + d[mt][3]) * wa1;
                p0 += __shfl_xor_sync(0xffffffffu, p0, 1);
                p0 += __shfl_xor_sync(0xffffffffu, p0, 2);
                p1 += __shfl_xor_sync(0xffffffffu, p1, 1);
                p1 += __shfl_xor_sync(0xffffffffu, p1, 2);
                if ((lane & 3) == 0) {
                    part[r0 * 16 + wid] = p0;
                    part[r1 * 16 + wid] = p1;
                }
            }
        }
        __syncthreads();

        // alpha[n] (x masked multiplicity), rows 0..99 of this phase
        if (tid < 100) {
            float a = 0.f;
            #pragma unroll
            for (int w = 0; w < 16; w++) a += part[tid * 16 + w];
            const int bt = (tid < 50) ? 0 : 1;
            const int n  = tid - bt * 50;
            const int g  = 2 * ph + bt;
            alpha_s[g * 64 + n] = a * (float)cnt_s[g * 64 + n];
        }
        __syncthreads();
    }

    // ---- session_graph for all 4 batches (nodes re-read, L2-hot) ----
    {
        const int bl = tid >> 7;          // 0..3
        const int c  = tid & 127;
        const int b  = b0 + bl;
        const float* nb = nodes + (size_t)b * NN * DD;
        const float* as = alpha_s + bl * 64;
        float sg = 0.f;
        #pragma unroll
        for (int n = 0; n < NN; n++)
            sg = fmaf(as[n], nb[n * DD + c], sg);
        out[(size_t)BB * DD + (size_t)b * DD + c] = sg;
    }
}

extern "C" void kernel_launch(void* const* d_in, const int* in_sizes, int n_in,
                              void* d_out, int out_size) {
    const int*   seq     = (const int*)  d_in[0];
    const int*   mask    = (const int*)  d_in[1];
    const float* nodes   = (const float*)d_in[2];
    // d_in[3] = batch_size scalar (compile-time constants used)
    const float* W_last  = (const float*)d_in[4];
    const float* W_seq   = (const float*)d_in[5];
    const float* b_seq   = (const float*)d_in[6];
    const float* W_alpha = (const float*)d_in[7];
    float* out = (float*)d_out;

    cudaFuncSetAttribute(combo_kernel, cudaFuncAttributeMaxDynamicSharedMemorySize, VN_SMEM);
    combo_kernel<<<160, 256, VN_SMEM>>>(seq, mask, nodes, W_last, W_seq, b_seq, out);

    cudaFuncSetAttribute(session_mma_kernel,
                         cudaFuncAttributeMaxDynamicSharedMemorySize, SMEM_TOTAL);
    session_mma_kernel<<<1024, TPB, SMEM_TOTAL>>>(seq, mask, nodes, W_alpha, out);
}

// round 14
// speedup vs baseline: 1.5081x; 1.5081x over previous
#include <cuda_runtime.h>
#include <cuda_bf16.h>
#include <cstdint>
#include <cstddef>

#define BB 4096
#define LL 50
#define NN 50
#define DD 128
#define PK 136                    // padded row stride (elements) -> 272B = 17*16: LDSM-aligned, conflict-free
#define TILE4 2176                // float4s per bf16 tile image (128*PK*2/16)
#define TPB 512

// ---- main-kernel smem layout (byte offsets) ----
#define WS_HI 0
#define WS_LO 34816
#define A_HI  69632
#define A_LO  104448
#define AUX   139264
#define AUX_CNT   (AUX + 0)       // int[4][64]
#define AUX_WA    (AUX + 1024)    // float[128]
#define AUX_VNP   (AUX + 1536)    // float[4][128]
#define AUX_ALPHA (AUX + 3584)    // float[4][64]
#define AUX_PART  (AUX + 4608)    // float[128][8]
#define SMEM_TOTAL (AUX + 8704)   // 147968

__device__ float g_vnp[BB * DD];
__device__ __align__(16) __nv_bfloat16 g_ws_hi[128 * PK];   // [n][k] transposed W_seq, hi
__device__ __align__(16) __nv_bfloat16 g_ws_lo[128 * PK];   // lo

__device__ __forceinline__ uint32_t smem_u32(const void* p) {
    uint32_t a;
    asm("{ .reg .u64 t; cvta.to.shared.u64 t, %1; cvt.u32.u64 %0, t; }" : "=r"(a) : "l"(p));
    return a;
}
__device__ __forceinline__ void ldsm_x4(uint32_t& r0, uint32_t& r1, uint32_t& r2, uint32_t& r3, uint32_t addr) {
    asm volatile("ldmatrix.sync.aligned.m8n8.x4.shared.b16 {%0,%1,%2,%3}, [%4];"
                 : "=r"(r0), "=r"(r1), "=r"(r2), "=r"(r3) : "r"(addr));
}
__device__ __forceinline__ void mma_bf16(float* d, uint32_t a0, uint32_t a1, uint32_t a2, uint32_t a3,
                                         uint32_t b0, uint32_t b1) {
    asm volatile("mma.sync.aligned.m16n8k16.row.col.f32.bf16.bf16.f32 "
                 "{%0,%1,%2,%3}, {%4,%5,%6,%7}, {%8,%9}, {%0,%1,%2,%3};"
                 : "+f"(d[0]), "+f"(d[1]), "+f"(d[2]), "+f"(d[3])
                 : "r"(a0), "r"(a1), "r"(a2), "r"(a3), "r"(b0), "r"(b1));
}
__device__ __forceinline__ float sigf(float z) {
    return 1.0f / (1.0f + __expf(-z));
}
__device__ __forceinline__ void cp_async16(uint32_t saddr, const void* gaddr) {
    asm volatile("cp.async.cg.shared.global [%0], [%1], 16;" :: "r"(saddr), "l"(gaddr));
}

// ============================================================
// Combo kernel: blocks 0..127 -> vn (32 batches each, W_last staged);
//               blocks 128..159 -> prep W_seq split images.
// ============================================================
#define VN_SMEM ((16384 + 128 + 8 * 128) * 4)
__global__ __launch_bounds__(256)
void combo_kernel(
    const int*   __restrict__ seq,
    const int*   __restrict__ mask,
    const float* __restrict__ nodes,
    const float* __restrict__ W_last,
    const float* __restrict__ W_seq,
    const float* __restrict__ b_seq,
    float*       __restrict__ out)
{
    extern __shared__ float dsm[];
    const int tid = threadIdx.x, wid = tid >> 5, lane = tid & 31;

    if (blockIdx.x >= 128) {
        // ---- prep: bake W_seq^T split-bf16 [n][k], stride PK ----
        const int base = (blockIdx.x - 128) * 512 + tid * 2;
        #pragma unroll
        for (int j = 0; j < 2; j++) {
            const int t = base + j;          // 0..16383
            const int k = t & 127, n = t >> 7;
            const float w = W_seq[k * DD + n];
            const __nv_bfloat16 h = __float2bfloat16(w);
            g_ws_hi[n * PK + k] = h;
            g_ws_lo[n * PK + k] = __float2bfloat16(w - __bfloat162float(h));
        }
        return;
    }

    // ---- vn: 32 batches per block ----
    float* wl_s = dsm;               // 16384
    float* bs_s = dsm + 16384;       // 128
    float* vnb  = dsm + 16512;       // 8 warps * 128
    const int b0 = blockIdx.x * 32;

    #pragma unroll
    for (int i = tid; i < 4096; i += 256)
        ((float4*)wl_s)[i] = ((const float4*)W_last)[i];
    if (tid < DD) bs_s[tid] = b_seq[tid];
    __syncthreads();

    for (int r = 0; r < 4; r++) {
        const int b = b0 + wid * 4 + r;
        int cnt = ((lane      < LL) ? mask[b * LL + lane]      : 0)
                + ((lane + 32 < LL) ? mask[b * LL + lane + 32] : 0);
        #pragma unroll
        for (int off = 16; off > 0; off >>= 1)
            cnt += __shfl_xor_sync(0xffffffffu, cnt, off);
        int last = 0;
        if (lane == 0)
            last = seq[b * LL + ((cnt > 0) ? cnt - 1 : LL - 1)];
        last = __shfl_sync(0xffffffffu, last, 0);

        const float4 v = ((const float4*)(nodes + (size_t)b * NN * DD + (size_t)last * DD))[lane];
        ((float4*)(out + (size_t)b * DD))[lane] = v;       // v_n output (exact copy)
        ((float4*)(vnb + wid * 128))[lane] = v;
        __syncwarp();

        float a0 = 0.f, a1 = 0.f, a2 = 0.f, a3 = 0.f;
        const float* vr = vnb + wid * 128;
        #pragma unroll 4
        for (int k = 0; k < 128; k++) {
            const float vk = vr[k];
            const float* wr = wl_s + k * 128 + lane;
            a0 = fmaf(vk, wr[0],  a0);
            a1 = fmaf(vk, wr[32], a1);
            a2 = fmaf(vk, wr[64], a2);
            a3 = fmaf(vk, wr[96], a3);
        }
        float* gv = g_vnp + (size_t)b * DD + lane;
        gv[0]  = a0 + bs_s[lane];
        gv[32] = a1 + bs_s[lane + 32];
        gv[64] = a2 + bs_s[lane + 64];
        gv[96] = a3 + bs_s[lane + 96];
        __syncwarp();
    }
}

// ============================================================
// Main: 4 batches/CTA (two A-phases), 512 threads / 16 warps.
// M-split: warps 0-7 own m-tiles 0-3, warps 8-15 own m-tiles 4-6.
// Each warp keeps 16 N-cols (ldsm_x4 B). A-LDSM traffic == R12.
// ============================================================
__global__ __launch_bounds__(TPB, 1)
void session_mma_kernel(
    const int*   __restrict__ seq,
    const int*   __restrict__ mask,
    const float* __restrict__ nodes,
    const float* __restrict__ W_alpha,
    float*       __restrict__ out)
{
    extern __shared__ char smem[];
    const uint32_t sb = smem_u32(smem);
    const int tid = threadIdx.x, wid = tid >> 5, lane = tid & 31;
    const int b0 = 4 * blockIdx.x;

    int*   cnt_s   = (int*)  (smem + AUX_CNT);
    float* wa_s    = (float*)(smem + AUX_WA);
    float* vnp_s   = (float*)(smem + AUX_VNP);
    float* alpha_s = (float*)(smem + AUX_ALPHA);
    float* part    = (float*)(smem + AUX_PART);

    // ---- kick off W image staging via cp.async (waited before phase-0 sync) ----
    {
        for (int i = tid; i < TILE4; i += TPB) {
            cp_async16(sb + WS_HI + i * 16, (const char*)g_ws_hi + i * 16);
            cp_async16(sb + WS_LO + i * 16, (const char*)g_ws_lo + i * 16);
        }
        asm volatile("cp.async.commit_group;");
    }

    if (tid < 256) cnt_s[tid] = 0;        // 4*64 ints
    if (tid < 128) wa_s[tid] = W_alpha[tid];
    // vnp for 4 batches (from combo kernel)
    vnp_s[tid] = g_vnp[(size_t)(b0 + (tid >> 7)) * DD + (tid & 127)];
    __syncthreads();

    // masked counts for 4 batches
    if (tid < 4 * LL) {
        const int bl = tid / LL, pos = tid % LL;
        const int g = (b0 + bl) * LL + pos;
        if (mask[g]) atomicAdd(&cnt_s[bl * 64 + seq[g]], 1);
    }
    // zero pad A rows 100..127 once (never overwritten by node conversion)
    for (int i = 1700 + tid; i < TILE4; i += TPB) {
        ((float4*)(smem + A_HI))[i] = make_float4(0.f, 0.f, 0.f, 0.f);
        ((float4*)(smem + A_LO))[i] = make_float4(0.f, 0.f, 0.f, 0.f);
    }

    const int lr  = lane & 7;
    const int g8  = (lane >> 3) & 1;
    const int g16 = lane >> 4;
    const int wn  = wid & 7;              // n-slot: 8 slots x 16 cols
    const int mg  = wid >> 3;             // m-group: 0 -> mt 0..3, 1 -> mt 4..6
    const int mt0 = mg * 4;
    const int mtN = mg ? 3 : 4;
    const int nbase = wn * 16;
    const uint32_t aRow = (uint32_t)(8 * g8 + lr) * (PK * 2) + (uint32_t)g16 * 16;
    const uint32_t bRow = (uint32_t)(nbase + 8 * g16 + lr) * (PK * 2) + (uint32_t)g8 * 16;

    #pragma unroll 1
    for (int ph = 0; ph < 2; ph++) {
        const int pb = b0 + 2 * ph;

        // ---- stage A: nodes (rows 0..99) -> split bf16, stride PK ----
        {
            const float4* nv = (const float4*)(nodes + (size_t)pb * NN * DD);
            #pragma unroll 2
            for (int i = tid; i < 3200; i += TPB) {
                const float4 x = nv[i];
                const int e = i * 4, row = e >> 7, k = e & 127;
                const __nv_bfloat16 h0 = __float2bfloat16(x.x);
                const __nv_bfloat16 h1 = __float2bfloat16(x.y);
                const __nv_bfloat16 h2 = __float2bfloat16(x.z);
                const __nv_bfloat16 h3 = __float2bfloat16(x.w);
                const __nv_bfloat16 l0 = __float2bfloat16(x.x - __bfloat162float(h0));
                const __nv_bfloat16 l1 = __float2bfloat16(x.y - __bfloat162float(h1));
                const __nv_bfloat16 l2 = __float2bfloat16(x.z - __bfloat162float(h2));
                const __nv_bfloat16 l3 = __float2bfloat16(x.w - __bfloat162float(h3));
                uint2 vh, vl;
                vh.x = (uint32_t)__bfloat16_as_ushort(h0) | ((uint32_t)__bfloat16_as_ushort(h1) << 16);
                vh.y = (uint32_t)__bfloat16_as_ushort(h2) | ((uint32_t)__bfloat16_as_ushort(h3) << 16);
                vl.x = (uint32_t)__bfloat16_as_ushort(l0) | ((uint32_t)__bfloat16_as_ushort(l1) << 16);
                vl.y = (uint32_t)__bfloat16_as_ushort(l2) | ((uint32_t)__bfloat16_as_ushort(l3) << 16);
                const uint32_t off = (uint32_t)row * (PK * 2) + (uint32_t)k * 2;  // 8B aligned
                *(uint2*)(smem + A_HI + off) = vh;
                *(uint2*)(smem + A_LO + off) = vl;
            }
        }
        if (ph == 0) asm volatile("cp.async.wait_group 0;" ::: "memory");
        __syncthreads();

        // ---- mma.sync mainloop: <=4 m-tiles x 2 n-tiles per warp, 8 k-steps, 3 passes ----
        float d[4][2][4];
        #pragma unroll
        for (int mt = 0; mt < 4; mt++)
            #pragma unroll
            for (int nt = 0; nt < 2; nt++)
                #pragma unroll
                for (int e = 0; e < 4; e++) d[mt][nt][e] = 0.f;

        #pragma unroll
        for (int pass = 0; pass < 3; pass++) {
            const uint32_t Ab = sb + ((pass == 2) ? A_LO : A_HI) + (uint32_t)mt0 * (16 * PK * 2);
            const uint32_t Bb = sb + ((pass == 1) ? WS_LO : WS_HI);
            #pragma unroll
            for (int ks = 0; ks < 8; ks++) {
                const uint32_t kb = (uint32_t)ks * 32;   // 16 elems * 2B
                uint32_t w0, w1, w2, w3;
                ldsm_x4(w0, w1, w2, w3, Bb + bRow + kb);
                #pragma unroll
                for (int mt = 0; mt < 4; mt++) {
                    if (mt < mtN) {
                        uint32_t a0, a1, a2, a3;
                        ldsm_x4(a0, a1, a2, a3, Ab + aRow + (uint32_t)mt * (16 * PK * 2) + kb);
                        mma_bf16(d[mt][0], a0, a1, a2, a3, w0, w1);
                        mma_bf16(d[mt][1], a0, a1, a2, a3, w2, w3);
                    }
                }
            }
        }

        // ---- epilogue: sigmoid, scale by W_alpha, row-wise reduce ----
        {
            const int q = lane & 3;
            #pragma unroll
            for (int mt = 0; mt < 4; mt++) {
                if (mt < mtN) {
                    const int r0 = 16 * (mt0 + mt) + (lane >> 2);
                    const int r1 = r0 + 8;
                    const float* vp0 = vnp_s + (2 * ph + ((r0 < 50) ? 0 : 1)) * 128;
                    const float* vp1 = vnp_s + (2 * ph + ((r1 < 50) ? 0 : 1)) * 128;
                    float p0 = 0.f, p1 = 0.f;
                    #pragma unroll
                    for (int nt = 0; nt < 2; nt++) {
                        const int c = nbase + nt * 8 + 2 * q;
                        const float wa0 = wa_s[c], wa1 = wa_s[c + 1];
                        p0 += sigf(vp0[c] + d[mt][nt][0]) * wa0 + sigf(vp0[c + 1] + d[mt][nt][1]) * wa1;
                        p1 += sigf(vp1[c] + d[mt][nt][2]) * wa0 + sigf(vp1[c + 1] + d[mt][nt][3]) * wa1;
                    }
                    p0 += __shfl_xor_sync(0xffffffffu, p0, 1);
                    p0 += __shfl_xor_sync(0xffffffffu, p0, 2);
                    p1 += __shfl_xor_sync(0xffffffffu, p1, 1);
                    p1 += __shfl_xor_sync(0xffffffffu, p1, 2);
                    if ((lane & 3) == 0) {
                        part[r0 * 8 + wn] = p0;
                        part[r1 * 8 + wn] = p1;
                    }
                }
            }
        }
        __syncthreads();

        // alpha[n] (x masked multiplicity), rows 0..99 of this phase
        if (tid < 100) {
            float a = 0.f;
            #pragma unroll
            for (int w = 0; w < 8; w++) a += part[tid * 8 + w];
            const int bt = (tid < 50) ? 0 : 1;
            const int n  = tid - bt * 50;
            const int g  = 2 * ph + bt;
            alpha_s[g * 64 + n] = a * (float)cnt_s[g * 64 + n];
        }
        __syncthreads();
    }

    // ---- session_graph for all 4 batches (nodes re-read, L2-hot) ----
    {
        const int bl = tid >> 7;          // 0..3
        const int c  = tid & 127;
        const int b  = b0 + bl;
        const float* nb = nodes + (size_t)b * NN * DD;
        const float* as = alpha_s + bl * 64;
        float sg = 0.f;
        #pragma unroll
        for (int n = 0; n < NN; n++)
            sg = fmaf(as[n], nb[n * DD + c], sg);
        out[(size_t)BB * DD + (size_t)b * DD + c] = sg;
    }
}

extern "C" void kernel_launch(void* const* d_in, const int* in_sizes, int n_in,
                              void* d_out, int out_size) {
    const int*   seq     = (const int*)  d_in[0];
    const int*   mask    = (const int*)  d_in[1];
    const float* nodes   = (const float*)d_in[2];
    // d_in[3] = batch_size scalar (compile-time constants used)
    const float* W_last  = (const float*)d_in[4];
    const float* W_seq   = (const float*)d_in[5];
    const float* b_seq   = (const float*)d_in[6];
    const float* W_alpha = (const float*)d_in[7];
    float* out = (float*)d_out;

    cudaFuncSetAttribute(combo_kernel, cudaFuncAttributeMaxDynamicSharedMemorySize, VN_SMEM);
    combo_kernel<<<160, 256, VN_SMEM>>>(seq, mask, nodes, W_last, W_seq, b_seq, out);

    cudaFuncSetAttribute(session_mma_kernel,
                         cudaFuncAttributeMaxDynamicSharedMemorySize, SMEM_TOTAL);
    session_mma_kernel<<<1024, TPB, SMEM_TOTAL>>>(seq, mask, nodes, W_alpha, out);
}